// round 3
// baseline (speedup 1.0000x reference)
#include <cuda_runtime.h>
#include <cuda_fp16.h>
#include <cstdint>

// ----------------------------------------------------------------------------
// Problem geometry:  out[4096 tokens][4096] = x[4096][4096] * W^T,
// W assembled from channel-weighted circulant blocks (FFT factorization is
// mathematically a dense block-circulant matmul; we materialize W once).
// ----------------------------------------------------------------------------
#define TOKENS 4096
#define KDIM   4096
#define NDIM   4096
#define NBLK   64
#define BLK    64
#define NMAT   4

#define MT 128
#define NT 128
#define KT 64
#define NITER (KDIM / KT)     // 64
#define STAGES 3

// Scratch (allocation-free rule: __device__ globals)
static __device__ __half g_A[(size_t)TOKENS * KDIM];   // x fp16, [M][K]
static __device__ __half g_W[(size_t)NDIM * KDIM];     // W fp16, [N][K] (K-major)

// ----------------------------------------------------------------------------
// Helpers
// ----------------------------------------------------------------------------
__device__ __forceinline__ uint32_t smem_u32(const void* p) {
    uint32_t a;
    asm("{ .reg .u64 t; cvta.to.shared.u64 t, %1; cvt.u32.u64 %0, t; }"
        : "=r"(a) : "l"(p));
    return a;
}

__device__ __forceinline__ void cp_async16(uint32_t dst, const void* src) {
    asm volatile("cp.async.cg.shared.global [%0], [%1], 16;\n"
                 :: "r"(dst), "l"(src));
}
#define CP_COMMIT() asm volatile("cp.async.commit_group;\n" ::: "memory")
#define CP_WAIT(n)  asm volatile("cp.async.wait_group %0;\n" :: "n"(n) : "memory")

__device__ __forceinline__ void ldsm_x4(uint32_t* r, uint32_t addr) {
    asm volatile("ldmatrix.sync.aligned.m8n8.x4.shared.b16 {%0,%1,%2,%3}, [%4];"
                 : "=r"(r[0]), "=r"(r[1]), "=r"(r[2]), "=r"(r[3]) : "r"(addr));
}

__device__ __forceinline__ void mma16816(float* d, const uint32_t* a,
                                         const uint32_t* b) {
    asm volatile(
        "mma.sync.aligned.m16n8k16.row.col.f32.f16.f16.f32 "
        "{%0,%1,%2,%3}, {%4,%5,%6,%7}, {%8,%9}, {%0,%1,%2,%3};\n"
        : "+f"(d[0]), "+f"(d[1]), "+f"(d[2]), "+f"(d[3])
        : "r"(a[0]), "r"(a[1]), "r"(a[2]), "r"(a[3]), "r"(b[0]), "r"(b[1]));
}

// ----------------------------------------------------------------------------
// Kernel 1: x fp32 -> fp16
// ----------------------------------------------------------------------------
__global__ void cvt_x(const float* __restrict__ x, int n4) {
    int i = blockIdx.x * blockDim.x + threadIdx.x;
    if (i < n4) {
        float4 v = reinterpret_cast<const float4*>(x)[i];
        union { __half2 h[2]; uint2 u; } pk;
        pk.h[0] = __floats2half2_rn(v.x, v.y);
        pk.h[1] = __floats2half2_rn(v.z, v.w);
        reinterpret_cast<uint2*>(g_A)[i] = pk.u;
    }
}

// ----------------------------------------------------------------------------
// Kernel 2: build W fp16.  cw[d] = sum_m w[m]*p[m,o,i,d];
// W[n=o*64+t][k=i*64+kk] = cw[(t-kk) mod 64]
// ----------------------------------------------------------------------------
__global__ void build_w(const float* __restrict__ p, const float* __restrict__ w) {
    const int oi = blockIdx.x;          // o*64 + i
    const int o = oi >> 6, i = oi & 63;
    const int t = threadIdx.x;          // 0..63
    __shared__ float cw[BLK];

    const float* base = p + (size_t)oi * BLK;
    float acc = 0.f;
#pragma unroll
    for (int m = 0; m < NMAT; ++m)
        acc += w[m] * base[(size_t)m * NBLK * NBLK * BLK + t];
    cw[t] = acc;
    __syncthreads();

    __half row[BLK];
#pragma unroll
    for (int kk = 0; kk < BLK; ++kk)
        row[kk] = __float2half_rn(cw[(t - kk) & 63]);

    uint4* dst = reinterpret_cast<uint4*>(g_W + (size_t)(o * 64 + t) * KDIM + i * 64);
    const uint4* src = reinterpret_cast<const uint4*>(row);
#pragma unroll
    for (int q = 0; q < 8; ++q) dst[q] = src[q];
}

// ----------------------------------------------------------------------------
// Kernel 3: GEMM via mma.sync (HMMA).  CTA 128x128, K-step 64, 3-stage cp.async.
// 8 warps in 2(M) x 4(N): each warp computes 64x32.
// SMEM per stage: A 128x64 f16 (16KB) + B 128x64 f16 (16KB).
// Swizzled layout: 128B rows, 16B chunk c stored at c ^ (row & 7).
// ----------------------------------------------------------------------------
static constexpr uint32_t STAGE_BYTES = 32768;
static constexpr uint32_t SMEM_BYTES = STAGES * STAGE_BYTES;   // 96 KB

__global__ void __launch_bounds__(256, 2)
gemm_hmma(float* __restrict__ out) {
    extern __shared__ __align__(1024) char smem[];
    const uint32_t sb = smem_u32(smem);
    const int tid = threadIdx.x;
    const int wid = tid >> 5;
    const int lane = tid & 31;
    const int m0 = (int)(blockIdx.x >> 5) * MT;
    const int n0 = (int)(blockIdx.x & 31) * NT;
    const int wm = (wid >> 2) * 64;        // warp M offset in tile
    const int wn = (wid & 3) * 32;         // warp N offset in tile

    const __half* Ag0 = g_A + (size_t)m0 * KDIM;
    const __half* Bg0 = g_W + (size_t)n0 * KDIM;

    // per-thread load coords (4 chunks each for A and B per stage)
    auto load_stage = [&](int s, int k0) {
        const uint32_t a_base = sb + (uint32_t)s * STAGE_BYTES;
        const uint32_t b_base = a_base + 16384;
#pragma unroll
        for (int i = 0; i < 4; ++i) {
            int idx = tid + i * 256;
            int r = idx >> 3, c = idx & 7;
            uint32_t soff = (uint32_t)(r * 128 + ((c ^ (r & 7)) << 4));
            cp_async16(a_base + soff, Ag0 + (size_t)r * KDIM + k0 + c * 8);
            cp_async16(b_base + soff, Bg0 + (size_t)r * KDIM + k0 + c * 8);
        }
    };

    float acc[4][4][4];
#pragma unroll
    for (int a = 0; a < 4; ++a)
#pragma unroll
        for (int b = 0; b < 4; ++b)
#pragma unroll
            for (int c = 0; c < 4; ++c) acc[a][b][c] = 0.f;

    load_stage(0, 0); CP_COMMIT();
    load_stage(1, KT); CP_COMMIT();

    int s_cur = 0, s_nxt = 2;
    for (int it = 0; it < NITER; ++it) {
        CP_WAIT(STAGES - 2);
        __syncthreads();

        const uint32_t a_base = sb + (uint32_t)s_cur * STAGE_BYTES;
        const uint32_t b_base = a_base + 16384;

#pragma unroll
        for (int kc = 0; kc < 4; ++kc) {
            uint32_t a_frag[4][4];
            uint32_t b_frag[2][4];
#pragma unroll
            for (int mt = 0; mt < 4; ++mt) {
                int row = wm + mt * 16 + (lane & 15);
                int chunk = kc * 2 + (lane >> 4);
                ldsm_x4(a_frag[mt],
                        a_base + row * 128 + ((chunk ^ (row & 7)) << 4));
            }
#pragma unroll
            for (int bt = 0; bt < 2; ++bt) {
                int row = wn + bt * 16 + (lane >> 4) * 8 + (lane & 7);
                int chunk = kc * 2 + ((lane & 15) >> 3);
                ldsm_x4(b_frag[bt],
                        b_base + row * 128 + ((chunk ^ (row & 7)) << 4));
            }
#pragma unroll
            for (int mt = 0; mt < 4; ++mt)
#pragma unroll
                for (int nt = 0; nt < 4; ++nt)
                    mma16816(acc[mt][nt], a_frag[mt],
                             &b_frag[nt >> 1][(nt & 1) * 2]);
        }

        int ni = it + STAGES - 1;
        if (ni < NITER) load_stage(s_nxt, ni * KT);
        CP_COMMIT();
        if (++s_cur == STAGES) s_cur = 0;
        if (++s_nxt == STAGES) s_nxt = 0;
    }

    // Epilogue: direct fp32 stores (float2 per fragment row)
#pragma unroll
    for (int mt = 0; mt < 4; ++mt) {
#pragma unroll
        for (int nt = 0; nt < 4; ++nt) {
            int row = m0 + wm + mt * 16 + (lane >> 2);
            int col = n0 + wn + nt * 8 + (lane & 3) * 2;
            *reinterpret_cast<float2*>(out + (size_t)row * NDIM + col) =
                make_float2(acc[mt][nt][0], acc[mt][nt][1]);
            *reinterpret_cast<float2*>(out + (size_t)(row + 8) * NDIM + col) =
                make_float2(acc[mt][nt][2], acc[mt][nt][3]);
        }
    }
}

// ----------------------------------------------------------------------------
// Host entry
// ----------------------------------------------------------------------------
extern "C" void kernel_launch(void* const* d_in, const int* in_sizes, int n_in,
                              void* d_out, int out_size) {
    const float* x       = (const float*)d_in[0];   // (2,2048,4096) f32
    const float* params  = (const float*)d_in[1];   // (4,64,64,64) f32
    const float* weights = (const float*)d_in[2];   // (4,) f32
    float* out = (float*)d_out;

    cvt_x<<<(TOKENS * KDIM / 4) / 256, 256>>>(x, TOKENS * KDIM / 4);
    build_w<<<NBLK * NBLK, BLK>>>(params, weights);

    cudaFuncSetAttribute(gemm_hmma, cudaFuncAttributeMaxDynamicSharedMemorySize,
                         SMEM_BYTES);
    gemm_hmma<<<(TOKENS / MT) * (NDIM / NT), 256, SMEM_BYTES>>>(out);
}

// round 5
// speedup vs baseline: 1.4424x; 1.4424x over previous
#include <cuda_runtime.h>
#include <cuda_fp16.h>
#include <cstdint>

// ----------------------------------------------------------------------------
// FFT-domain block-circulant matmul.
//   x:(2,2048,4096) f32 -> out:(2,2048,4096) f32
//   TOKENS=4096 tokens, 64 blocks of 64; 33 rfft frequencies.
// Pipeline (all tensor-core GEMMs, fp16 operands / fp32 accum):
//   K_W : W_f = rfft(sum_m w_m * params_m)         -> Wr/Wi/Wmi [f][o][i] fp16
//   K1  : X_f = x_blocks @ DFT(64x66)              -> Xr/Xi [f][t][i] fp16
//   K2  : Y_f = X_f @ W_f  (complex, per f)        -> Yr/Yi [f][t][o] fp16
//   K3  : out = [Yr|Yi] @ iDFT(66x64)              -> f32, direct layout match
// ----------------------------------------------------------------------------
#define TOKENS 4096
#define NBLK   64
#define BLK    64
#define NMAT   4
#define NFREQ  33
#define RROWS  (TOKENS * NBLK)      // 262144  (t,i) and (t,o) row counts

static __device__ __half g_Xr[(size_t)NFREQ * RROWS];
static __device__ __half g_Xi[(size_t)NFREQ * RROWS];
static __device__ __half g_Yr[(size_t)NFREQ * RROWS];
static __device__ __half g_Yi[(size_t)NFREQ * RROWS];
static __device__ __half g_Wr[NFREQ * NBLK * BLK];
static __device__ __half g_Wi[NFREQ * NBLK * BLK];
static __device__ __half g_Wmi[NFREQ * NBLK * BLK];   // -Wi

// ----------------------------------------------------------------------------
// Helpers
// ----------------------------------------------------------------------------
__device__ __forceinline__ uint32_t smem_u32(const void* p) {
    uint32_t a;
    asm("{ .reg .u64 t; cvta.to.shared.u64 t, %1; cvt.u32.u64 %0, t; }"
        : "=r"(a) : "l"(p));
    return a;
}

__device__ __forceinline__ void cp_async16(uint32_t dst, const void* src) {
    asm volatile("cp.async.cg.shared.global [%0], [%1], 16;\n"
                 :: "r"(dst), "l"(src));
}
#define CP_COMMIT() asm volatile("cp.async.commit_group;\n" ::: "memory")
#define CP_WAIT0()  asm volatile("cp.async.wait_group 0;\n" ::: "memory")

__device__ __forceinline__ void ldsm_x4(uint32_t* r, uint32_t addr) {
    asm volatile("ldmatrix.sync.aligned.m8n8.x4.shared.b16 {%0,%1,%2,%3}, [%4];"
                 : "=r"(r[0]), "=r"(r[1]), "=r"(r[2]), "=r"(r[3]) : "r"(addr));
}

__device__ __forceinline__ void mma16816(float* d, const uint32_t* a,
                                         const uint32_t* b) {
    asm volatile(
        "mma.sync.aligned.m16n8k16.row.col.f32.f16.f16.f32 "
        "{%0,%1,%2,%3}, {%4,%5,%6,%7}, {%8,%9}, {%0,%1,%2,%3};\n"
        : "+f"(d[0]), "+f"(d[1]), "+f"(d[2]), "+f"(d[3])
        : "r"(a[0]), "r"(a[1]), "r"(a[2]), "r"(a[3]), "r"(b[0]), "r"(b[1]));
}

// ----------------------------------------------------------------------------
// K_W: weight FFT.  One block per (o,i); 64 threads.
// cw[d] = sum_m w[m]*p[m,o,i,d];  Wr[f]=sum cw*cos(2pi f d/64); Wi=-sum cw*sin.
// ----------------------------------------------------------------------------
__global__ void __launch_bounds__(64) kw_fft(const float* __restrict__ p,
                                             const float* __restrict__ w) {
    __shared__ float cw[BLK];
    __shared__ float ct[64], st[64];
    const int oi = blockIdx.x;        // o*64+i
    const int t = threadIdx.x;

    ct[t] = cospif(t / 32.f);
    st[t] = sinpif(t / 32.f);

    float acc = 0.f;
#pragma unroll
    for (int m = 0; m < NMAT; ++m)
        acc += w[m] * p[(size_t)m * (NBLK * NBLK * BLK) + (size_t)oi * BLK + t];
    cw[t] = acc;
    __syncthreads();

    if (t < NFREQ) {
        float wr = 0.f, wi = 0.f;
#pragma unroll
        for (int d = 0; d < BLK; ++d) {
            int k = (t * d) & 63;
            wr += cw[d] * ct[k];
            wi -= cw[d] * st[k];
        }
        const int off = t * (NBLK * BLK) + oi;    // [f][o][i]
        g_Wr[off]  = __float2half_rn(wr);
        g_Wi[off]  = __float2half_rn(wi);
        g_Wmi[off] = __float2half_rn(-wi);
    }
}

// ----------------------------------------------------------------------------
// K1: forward DFT GEMM.  M=262144 (r=t*64+i), N=66(->pad 80), K=64.
// CTA: 128 rows, 128 threads (4 warps, each 32 rows x all N).
// A smem: 128x64 f16 swizzled (16KB @0). B smem: 80x64 f16 swizzled (10KB @16K).
// Epilogue: smem transpose (72x128 f16 @0) -> coalesced plane stores.
// ----------------------------------------------------------------------------
__global__ void __launch_bounds__(128) k1_dft(const float* __restrict__ x) {
    __shared__ __align__(128) char sm[26624];
    __shared__ float ct[64], st[64];
    const uint32_t sb = smem_u32(sm);
    const int tid = threadIdx.x;
    const int wid = tid >> 5, lane = tid & 31;
    const int r0 = (int)blockIdx.x * 128;

    if (tid < 64) { ct[tid] = cospif(tid / 32.f); st[tid] = sinpif(tid / 32.f); }

    // A: x[r0+r][d], fp32->fp16, swizzled rows of 128B
#pragma unroll
    for (int it = 0; it < 8; ++it) {
        int idx = tid + it * 128;          // 1024 chunks (r,c)
        int r = idx >> 3, c = idx & 7;
        const float4* src = reinterpret_cast<const float4*>(
            x + (size_t)(r0 + r) * 64 + c * 8);
        float4 v0 = src[0], v1 = src[1];
        union { __half2 h[4]; uint4 u; } pk;
        pk.h[0] = __floats2half2_rn(v0.x, v0.y);
        pk.h[1] = __floats2half2_rn(v0.z, v0.w);
        pk.h[2] = __floats2half2_rn(v1.x, v1.y);
        pk.h[3] = __floats2half2_rn(v1.z, v1.w);
        *reinterpret_cast<uint4*>(sm + r * 128 + ((c ^ (r & 7)) << 4)) = pk.u;
    }
    __syncthreads();    // tables ready

    // B: rows f'=0..32 cos, 33..65 -sin, 66..79 zero (swizzled @16384)
    if (tid < 80) {
        const int f2 = tid;
#pragma unroll 8
        for (int d = 0; d < 64; ++d) {
            float v = 0.f;
            if (f2 < 33)       v = ct[(f2 * d) & 63];
            else if (f2 < 66)  v = -st[((f2 - 33) * d) & 63];
            int c = d >> 3;
            *reinterpret_cast<__half*>(
                sm + 16384 + f2 * 128 + ((c ^ (f2 & 7)) << 4) + (d & 7) * 2) =
                __float2half_rn(v);
        }
    }
    __syncthreads();

    const int wm = wid * 32;
    float acc[2][9][4] = {};
#pragma unroll
    for (int kc = 0; kc < 4; ++kc) {
        uint32_t a[2][4], b[5][4];
#pragma unroll
        for (int mt = 0; mt < 2; ++mt) {
            int row = wm + mt * 16 + (lane & 15);
            int ch = kc * 2 + (lane >> 4);
            ldsm_x4(a[mt], sb + row * 128 + ((ch ^ (row & 7)) << 4));
        }
#pragma unroll
        for (int bt = 0; bt < 5; ++bt) {
            int row = bt * 16 + (lane >> 4) * 8 + (lane & 7);
            int ch = kc * 2 + ((lane & 15) >> 3);
            ldsm_x4(b[bt], sb + 16384 + row * 128 + ((ch ^ (row & 7)) << 4));
        }
#pragma unroll
        for (int mt = 0; mt < 2; ++mt)
#pragma unroll
            for (int nt = 0; nt < 9; ++nt)
                mma16816(acc[mt][nt], a[mt], &b[nt >> 1][(nt & 1) * 2]);
    }
    __syncthreads();

    // transpose to [f'][r] (72 x 128 f16 @0)
#pragma unroll
    for (int mt = 0; mt < 2; ++mt)
#pragma unroll
        for (int nt = 0; nt < 9; ++nt) {
            int row = wm + mt * 16 + (lane >> 2);
            int col = nt * 8 + (lane & 3) * 2;
            *reinterpret_cast<__half*>(sm + col * 256 + row * 2) =
                __float2half_rn(acc[mt][nt][0]);
            *reinterpret_cast<__half*>(sm + (col + 1) * 256 + row * 2) =
                __float2half_rn(acc[mt][nt][1]);
            *reinterpret_cast<__half*>(sm + col * 256 + (row + 8) * 2) =
                __float2half_rn(acc[mt][nt][2]);
            *reinterpret_cast<__half*>(sm + (col + 1) * 256 + (row + 8) * 2) =
                __float2half_rn(acc[mt][nt][3]);
        }
    __syncthreads();

    // coalesced plane stores: 66 rows x 64 u32
#pragma unroll
    for (int it = 0; it < 33; ++it) {
        int idx = tid + it * 128;       // 4224 = 66*64
        int f2 = idx >> 6, c = idx & 63;
        uint32_t v = *reinterpret_cast<uint32_t*>(sm + f2 * 256 + c * 4);
        __half* plane = (f2 < 33) ? (g_Xr + (size_t)f2 * RROWS)
                                  : (g_Xi + (size_t)(f2 - 33) * RROWS);
        reinterpret_cast<uint32_t*>(plane + r0)[c] = v;
    }
}

// ----------------------------------------------------------------------------
// K2: per-frequency complex GEMM.  grid = 33 * 32; CTA = 128 tokens x 64 o.
// smem (dynamic 57344): Xr@0 Xi@16384 (128x64 ea), Wr@32768 Wi@40960 Wmi@49152.
// 8 warps, 4(M) x 2(N), each 32x32.
// ----------------------------------------------------------------------------
__global__ void __launch_bounds__(256) k2_cgemm() {
    extern __shared__ __align__(128) char dsm[];
    const uint32_t sb = smem_u32(dsm);
    const int tid = threadIdx.x;
    const int wid = tid >> 5, lane = tid & 31;
    const int f = (int)blockIdx.x >> 5;
    const int t0 = ((int)blockIdx.x & 31) * 128;

    const __half* Xr = g_Xr + (size_t)f * RROWS + (size_t)t0 * 64;
    const __half* Xi = g_Xi + (size_t)f * RROWS + (size_t)t0 * 64;
    const __half* Wr = g_Wr + f * (NBLK * BLK);
    const __half* Wi = g_Wi + f * (NBLK * BLK);
    const __half* Wmi = g_Wmi + f * (NBLK * BLK);

#pragma unroll
    for (int it = 0; it < 4; ++it) {      // X tiles: 1024 chunks each
        int idx = tid + it * 256;
        int r = idx >> 3, c = idx & 7;
        uint32_t soff = (uint32_t)(r * 128 + ((c ^ (r & 7)) << 4));
        cp_async16(sb + soff, Xr + (size_t)r * 64 + c * 8);
        cp_async16(sb + 16384 + soff, Xi + (size_t)r * 64 + c * 8);
    }
#pragma unroll
    for (int it = 0; it < 2; ++it) {      // W tiles: 512 chunks each
        int idx = tid + it * 256;
        int r = idx >> 3, c = idx & 7;
        uint32_t soff = (uint32_t)(r * 128 + ((c ^ (r & 7)) << 4));
        cp_async16(sb + 32768 + soff, Wr + r * 64 + c * 8);
        cp_async16(sb + 40960 + soff, Wi + r * 64 + c * 8);
        cp_async16(sb + 49152 + soff, Wmi + r * 64 + c * 8);
    }
    CP_COMMIT();
    CP_WAIT0();
    __syncthreads();

    const int wm = (wid >> 1) * 32;
    const int wn = (wid & 1) * 32;
    float aR[2][4][4] = {}, aI[2][4][4] = {};

#pragma unroll
    for (int kc = 0; kc < 4; ++kc) {
        uint32_t ar[2][4], ai[2][4], br[2][4], bi[2][4], bmi[2][4];
#pragma unroll
        for (int mt = 0; mt < 2; ++mt) {
            int row = wm + mt * 16 + (lane & 15);
            int ch = kc * 2 + (lane >> 4);
            uint32_t soff = (uint32_t)(row * 128 + ((ch ^ (row & 7)) << 4));
            ldsm_x4(ar[mt], sb + soff);
            ldsm_x4(ai[mt], sb + 16384 + soff);
        }
#pragma unroll
        for (int bt = 0; bt < 2; ++bt) {
            int row = wn + bt * 16 + (lane >> 4) * 8 + (lane & 7);
            int ch = kc * 2 + ((lane & 15) >> 3);
            uint32_t soff = (uint32_t)(row * 128 + ((ch ^ (row & 7)) << 4));
            ldsm_x4(br[bt], sb + 32768 + soff);
            ldsm_x4(bi[bt], sb + 40960 + soff);
            ldsm_x4(bmi[bt], sb + 49152 + soff);
        }
#pragma unroll
        for (int mt = 0; mt < 2; ++mt)
#pragma unroll
            for (int nt = 0; nt < 4; ++nt) {
                mma16816(aR[mt][nt], ar[mt], &br[nt >> 1][(nt & 1) * 2]);
                mma16816(aR[mt][nt], ai[mt], &bmi[nt >> 1][(nt & 1) * 2]);
                mma16816(aI[mt][nt], ar[mt], &bi[nt >> 1][(nt & 1) * 2]);
                mma16816(aI[mt][nt], ai[mt], &br[nt >> 1][(nt & 1) * 2]);
            }
    }

    __half* Yr = g_Yr + (size_t)f * RROWS + (size_t)t0 * 64;
    __half* Yi = g_Yi + (size_t)f * RROWS + (size_t)t0 * 64;
#pragma unroll
    for (int mt = 0; mt < 2; ++mt)
#pragma unroll
        for (int nt = 0; nt < 4; ++nt) {
            int row = wm + mt * 16 + (lane >> 2);
            int col = wn + nt * 8 + (lane & 3) * 2;
            *reinterpret_cast<__half2*>(Yr + (size_t)row * 64 + col) =
                __floats2half2_rn(aR[mt][nt][0], aR[mt][nt][1]);
            *reinterpret_cast<__half2*>(Yr + (size_t)(row + 8) * 64 + col) =
                __floats2half2_rn(aR[mt][nt][2], aR[mt][nt][3]);
            *reinterpret_cast<__half2*>(Yi + (size_t)row * 64 + col) =
                __floats2half2_rn(aI[mt][nt][0], aI[mt][nt][1]);
            *reinterpret_cast<__half2*>(Yi + (size_t)(row + 8) * 64 + col) =
                __floats2half2_rn(aI[mt][nt][2], aI[mt][nt][3]);
        }
}

// ----------------------------------------------------------------------------
// K3: inverse DFT GEMM.  M=262144 (r=t*64+o), N=64 (d), K=66 -> pad 80.
// A smem: 128x80 f16, row stride 160B (no swizzle). B: 64x80, stride 160B.
// out[(r0+r)*64+d] is exactly the flat output layout.
// ----------------------------------------------------------------------------
__global__ void __launch_bounds__(128) k3_idft(float* __restrict__ out) {
    __shared__ __align__(128) char sa[128 * 160];
    __shared__ __align__(128) char sbm[64 * 160];
    __shared__ float ct[64], st[64];
    const uint32_t sa32 = smem_u32(sa);
    const uint32_t sb32 = smem_u32(sbm);
    const int tid = threadIdx.x;
    const int wid = tid >> 5, lane = tid & 31;
    const int r0 = (int)blockIdx.x * 128;

    if (tid < 64) { ct[tid] = cospif(tid / 32.f); st[tid] = sinpif(tid / 32.f); }

    // A load: row = tid, columns k: 0..32 Yr, 33..65 Yi, 66..79 zero
    {
        char* arow = sa + tid * 160;
#pragma unroll 11
        for (int k = 0; k < 33; ++k) {
            *reinterpret_cast<__half*>(arow + k * 2) =
                g_Yr[(size_t)k * RROWS + r0 + tid];
            *reinterpret_cast<__half*>(arow + (33 + k) * 2) =
                g_Yi[(size_t)k * RROWS + r0 + tid];
        }
#pragma unroll
        for (int k = 66; k < 80; ++k)
            *reinterpret_cast<__half*>(arow + k * 2) = __half(0.f);
    }
    __syncthreads();   // tables ready

    // B: row d (tid<64), cols k: gc/gs
    if (tid < 64) {
        const int d = tid;
        char* brow = sbm + d * 160;
#pragma unroll 10
        for (int k = 0; k < 80; ++k) {
            float v = 0.f;
            if (k < 33) {
                float wf = (k == 0 || k == 32) ? 1.f : 2.f;
                v = wf * ct[(k * d) & 63] * (1.f / 64.f);
            } else if (k < 66) {
                int fq = k - 33;
                float wf = (fq == 0 || fq == 32) ? 1.f : 2.f;
                v = -wf * st[(fq * d) & 63] * (1.f / 64.f);
            }
            *reinterpret_cast<__half*>(brow + k * 2) = __float2half_rn(v);
        }
    }
    __syncthreads();

    const int wm = wid * 32;
    float acc[2][8][4] = {};
#pragma unroll
    for (int kc = 0; kc < 5; ++kc) {
        uint32_t a[2][4], b[4][4];
#pragma unroll
        for (int mt = 0; mt < 2; ++mt) {
            int row = wm + mt * 16 + (lane & 15);
            int ch = kc * 2 + (lane >> 4);
            ldsm_x4(a[mt], sa32 + row * 160 + ch * 16);
        }
#pragma unroll
        for (int bt = 0; bt < 4; ++bt) {
            int row = bt * 16 + (lane >> 4) * 8 + (lane & 7);
            int ch = kc * 2 + ((lane & 15) >> 3);
            ldsm_x4(b[bt], sb32 + row * 160 + ch * 16);
        }
#pragma unroll
        for (int mt = 0; mt < 2; ++mt)
#pragma unroll
            for (int nt = 0; nt < 8; ++nt)
                mma16816(acc[mt][nt], a[mt], &b[nt >> 1][(nt & 1) * 2]);
    }

#pragma unroll
    for (int mt = 0; mt < 2; ++mt)
#pragma unroll
        for (int nt = 0; nt < 8; ++nt) {
            int row = wm + mt * 16 + (lane >> 2);
            int col = nt * 8 + (lane & 3) * 2;
            *reinterpret_cast<float2*>(out + (size_t)(r0 + row) * 64 + col) =
                make_float2(acc[mt][nt][0], acc[mt][nt][1]);
            *reinterpret_cast<float2*>(out + (size_t)(r0 + row + 8) * 64 + col) =
                make_float2(acc[mt][nt][2], acc[mt][nt][3]);
        }
}

// ----------------------------------------------------------------------------
// Host entry
// ----------------------------------------------------------------------------
extern "C" void kernel_launch(void* const* d_in, const int* in_sizes, int n_in,
                              void* d_out, int out_size) {
    const float* x       = (const float*)d_in[0];   // (2,2048,4096) f32
    const float* params  = (const float*)d_in[1];   // (4,64,64,64) f32
    const float* weights = (const float*)d_in[2];   // (4,) f32
    float* out = (float*)d_out;

    kw_fft<<<NBLK * NBLK, 64>>>(params, weights);
    k1_dft<<<RROWS / 128, 128>>>(x);

    cudaFuncSetAttribute(k2_cgemm, cudaFuncAttributeMaxDynamicSharedMemorySize,
                         57344);
    k2_cgemm<<<NFREQ * 32, 256, 57344>>>();

    k3_idft<<<RROWS / 128, 128>>>(out);
}

// round 8
// speedup vs baseline: 3.3420x; 2.3169x over previous
#include <cuda_runtime.h>
#include <cuda_fp16.h>
#include <cstdint>

// ----------------------------------------------------------------------------
// FFT-domain block-circulant matmul.
//   K_T : build constant DFT / iDFT operand images (pre-swizzled)
//   K_W : W planes, complex-interleaved over k2=2i+{r,i}:  BWr/BWi [f][o][128]
//   K1  : X2[f][r] = half2(Xr,Xi)  (forward DFT GEMM, transposed epilogue)
//   K2  : Y2[f][r] = half2(Yr,Yi)  (per-f GEMM, K=128 interleaved contraction)
//   K3  : out = [Y2 rows] @ iDFT   (A rows contiguous -> cp.async 4B)
// ----------------------------------------------------------------------------
#define TOKENS 4096
#define NBLK   64
#define BLK    64
#define NMAT   4
#define NFREQ  33
#define RROWS  (TOKENS * NBLK)      // 262144

static __device__ __half2 g_X2[(size_t)NFREQ * RROWS];
static __device__ __half2 g_Y2[(size_t)NFREQ * RROWS];
static __device__ __half g_WBr[(size_t)NFREQ * NBLK * 128];
static __device__ __half g_WBi[(size_t)NFREQ * NBLK * 128];
static __device__ __half g_Bf_img[80 * 64];    // fwd DFT, swizzled image (10KB)
static __device__ __half g_Bi_img[64 * 88];    // iDFT, padded rows 176B (11KB)

// ----------------------------------------------------------------------------
// Helpers
// ----------------------------------------------------------------------------
__device__ __forceinline__ uint32_t h2u(__half2 v) {
    union { __half2 h; uint32_t u; } c;
    c.h = v;
    return c.u;
}

__device__ __forceinline__ uint32_t smem_u32(const void* p) {
    uint32_t a;
    asm("{ .reg .u64 t; cvta.to.shared.u64 t, %1; cvt.u32.u64 %0, t; }"
        : "=r"(a) : "l"(p));
    return a;
}

__device__ __forceinline__ void cp_async16(uint32_t dst, const void* src) {
    asm volatile("cp.async.cg.shared.global [%0], [%1], 16;\n"
                 :: "r"(dst), "l"(src));
}
__device__ __forceinline__ void cp_async4(uint32_t dst, const void* src) {
    asm volatile("cp.async.ca.shared.global [%0], [%1], 4;\n"
                 :: "r"(dst), "l"(src));
}
#define CP_COMMIT() asm volatile("cp.async.commit_group;\n" ::: "memory")
#define CP_WAIT0()  asm volatile("cp.async.wait_group 0;\n" ::: "memory")

__device__ __forceinline__ void ldsm_x4(uint32_t* r, uint32_t addr) {
    asm volatile("ldmatrix.sync.aligned.m8n8.x4.shared.b16 {%0,%1,%2,%3}, [%4];"
                 : "=r"(r[0]), "=r"(r[1]), "=r"(r[2]), "=r"(r[3]) : "r"(addr));
}

__device__ __forceinline__ void mma16816(float* d, const uint32_t* a,
                                         const uint32_t* b) {
    asm volatile(
        "mma.sync.aligned.m16n8k16.row.col.f32.f16.f16.f32 "
        "{%0,%1,%2,%3}, {%4,%5,%6,%7}, {%8,%9}, {%0,%1,%2,%3};\n"
        : "+f"(d[0]), "+f"(d[1]), "+f"(d[2]), "+f"(d[3])
        : "r"(a[0]), "r"(a[1]), "r"(a[2]), "r"(a[3]), "r"(b[0]), "r"(b[1]));
}

// ----------------------------------------------------------------------------
// K_T: constant operand images (1 block, 128 threads)
// ----------------------------------------------------------------------------
__global__ void __launch_bounds__(128) k_tables() {
    __shared__ float ct[64], st[64];
    const int tid = threadIdx.x;
    if (tid < 64) { ct[tid] = cospif(tid / 32.f); st[tid] = sinpif(tid / 32.f); }
    __syncthreads();

    // forward: rows f2 0..79 (0..32 cos, 33..65 -sin, rest 0), cols d 0..63,
    // stored at the swizzled smem-image position used by K1's ldmatrix.
    for (int idx = tid; idx < 80 * 64; idx += 128) {
        int f2 = idx >> 6, d = idx & 63;
        float v = 0.f;
        if (f2 < 33)      v = ct[(f2 * d) & 63];
        else if (f2 < 66) v = -st[((f2 - 33) * d) & 63];
        int pos = f2 * 64 + ((((d >> 3) ^ (f2 & 7)) << 3) | (d & 7));
        g_Bf_img[pos] = __float2half_rn(v);
    }
    // inverse: rows d 0..63 (88 halves = 176B padded), cols k=2f+ri
    for (int idx = tid; idx < 64 * 88; idx += 128) {
        int d = idx / 88, k = idx % 88;
        float v = 0.f;
        if (k < 66) {
            int f = k >> 1;
            float wf = (f == 0 || f == 32) ? (1.f / 64.f) : (2.f / 64.f);
            v = (k & 1) ? -wf * st[(f * d) & 63] : wf * ct[(f * d) & 63];
        }
        g_Bi_img[idx] = __float2half_rn(v);
    }
}

// ----------------------------------------------------------------------------
// K_W: weight FFT -> interleaved B planes.  One block per (o,i); 64 threads.
// ----------------------------------------------------------------------------
__global__ void __launch_bounds__(64) kw_fft(const float* __restrict__ p,
                                             const float* __restrict__ w) {
    __shared__ float cw[BLK];
    __shared__ float ct[64], st[64];
    const int oi = blockIdx.x;        // o*64+i
    const int o = oi >> 6, i = oi & 63;
    const int t = threadIdx.x;

    ct[t] = cospif(t / 32.f);
    st[t] = sinpif(t / 32.f);

    float acc = 0.f;
#pragma unroll
    for (int m = 0; m < NMAT; ++m)
        acc += w[m] * p[(size_t)m * (NBLK * NBLK * BLK) + (size_t)oi * BLK + t];
    cw[t] = acc;
    __syncthreads();

    if (t < NFREQ) {
        float wr = 0.f, wi = 0.f;
#pragma unroll
        for (int d = 0; d < BLK; ++d) {
            int k = (t * d) & 63;
            wr += cw[d] * ct[k];
            wi -= cw[d] * st[k];
        }
        const size_t base = ((size_t)t * NBLK + o) * 128 + 2 * i;
        g_WBr[base]     = __float2half_rn(wr);
        g_WBr[base + 1] = __float2half_rn(-wi);
        g_WBi[base]     = __float2half_rn(wi);
        g_WBi[base + 1] = __float2half_rn(wr);
    }
}

// ----------------------------------------------------------------------------
// K1: forward DFT GEMM.  M=262144 (r=t*64+i), N=66(->72), K=64.
// 128 threads, 128 rows/CTA.  A smem 128x128B swizzled @0; B image @16384.
// Epilogue: smem transpose then interleaved half2 plane stores to g_X2.
// ----------------------------------------------------------------------------
__global__ void __launch_bounds__(128) k1_dft(const float* __restrict__ x) {
    __shared__ __align__(128) char sm[26624];
    const uint32_t sb = smem_u32(sm);
    const int tid = threadIdx.x;
    const int wid = tid >> 5, lane = tid & 31;
    const int r0 = (int)blockIdx.x * 128;

    // B image: 640 x 16B
#pragma unroll
    for (int it = 0; it < 5; ++it) {
        int chunk = tid + it * 128;
        cp_async16(sb + 16384 + chunk * 16, g_Bf_img + chunk * 8);
    }
    CP_COMMIT();

    // A: fp32 -> fp16, swizzled rows of 128B
#pragma unroll
    for (int it = 0; it < 8; ++it) {
        int idx = tid + it * 128;
        int r = idx >> 3, c = idx & 7;
        const float4* src = reinterpret_cast<const float4*>(
            x + (size_t)(r0 + r) * 64 + c * 8);
        float4 v0 = src[0], v1 = src[1];
        union { __half2 h[4]; uint4 u; } pk;
        pk.h[0] = __floats2half2_rn(v0.x, v0.y);
        pk.h[1] = __floats2half2_rn(v0.z, v0.w);
        pk.h[2] = __floats2half2_rn(v1.x, v1.y);
        pk.h[3] = __floats2half2_rn(v1.z, v1.w);
        *reinterpret_cast<uint4*>(sm + r * 128 + ((c ^ (r & 7)) << 4)) = pk.u;
    }
    CP_WAIT0();
    __syncthreads();

    const int wm = wid * 32;
    float acc[2][9][4] = {};
#pragma unroll
    for (int kc = 0; kc < 4; ++kc) {
        uint32_t a[2][4], b[5][4];
#pragma unroll
        for (int mt = 0; mt < 2; ++mt) {
            int row = wm + mt * 16 + (lane & 15);
            int ch = kc * 2 + (lane >> 4);
            ldsm_x4(a[mt], sb + row * 128 + ((ch ^ (row & 7)) << 4));
        }
#pragma unroll
        for (int bt = 0; bt < 5; ++bt) {
            int row = bt * 16 + (lane >> 4) * 8 + (lane & 7);
            int ch = kc * 2 + ((lane & 15) >> 3);
            ldsm_x4(b[bt], sb + 16384 + row * 128 + ((ch ^ (row & 7)) << 4));
        }
#pragma unroll
        for (int mt = 0; mt < 2; ++mt)
#pragma unroll
            for (int nt = 0; nt < 9; ++nt)
                mma16816(acc[mt][nt], a[mt], &b[nt >> 1][(nt & 1) * 2]);
    }
    __syncthreads();

    // transpose to [f'][r] (72 x 128 f16 @0, 256B per f')
#pragma unroll
    for (int mt = 0; mt < 2; ++mt)
#pragma unroll
        for (int nt = 0; nt < 9; ++nt) {
            int row = wm + mt * 16 + (lane >> 2);
            int col = nt * 8 + (lane & 3) * 2;
            *reinterpret_cast<__half*>(sm + col * 256 + row * 2) =
                __float2half_rn(acc[mt][nt][0]);
            *reinterpret_cast<__half*>(sm + (col + 1) * 256 + row * 2) =
                __float2half_rn(acc[mt][nt][1]);
            *reinterpret_cast<__half*>(sm + col * 256 + (row + 8) * 2) =
                __float2half_rn(acc[mt][nt][2]);
            *reinterpret_cast<__half*>(sm + (col + 1) * 256 + (row + 8) * 2) =
                __float2half_rn(acc[mt][nt][3]);
        }
    __syncthreads();

    // interleaved plane stores: g_X2[f][r] = (Xr, Xi)
#pragma unroll
    for (int f = 0; f < NFREQ; ++f) {
        __half lo = *reinterpret_cast<__half*>(sm + f * 256 + tid * 2);
        __half hi = *reinterpret_cast<__half*>(sm + (f + 33) * 256 + tid * 2);
        reinterpret_cast<uint32_t*>(g_X2)[(size_t)f * RROWS + r0 + tid] =
            h2u(__halves2half2(lo, hi));
    }
}

// ----------------------------------------------------------------------------
// K2: per-frequency GEMM, K=128 interleaved complex contraction.
// grid = 33*32; CTA = 256 thr, 128 tokens x 64 o.
// smem: A(X2) 128x256B @0 (32KB), BWr @32768, BWi @49152 (16KB each).
// ----------------------------------------------------------------------------
__device__ __forceinline__ uint32_t sw256(int row, int ch) {
    return (uint32_t)(row * 256 + ((ch >> 3) << 7) + ((((ch & 7) ^ (row & 7))) << 4));
}

__global__ void __launch_bounds__(256, 2) k2_cgemm() {
    extern __shared__ __align__(128) char dsm[];
    const uint32_t sb = smem_u32(dsm);
    const int tid = threadIdx.x;
    const int wid = tid >> 5, lane = tid & 31;
    const int f = (int)blockIdx.x >> 5;
    const int t0 = ((int)blockIdx.x & 31) * 128;

    const char* Xsrc = reinterpret_cast<const char*>(g_X2) +
                       ((size_t)f * RROWS + (size_t)t0 * 64) * 4;
    const __half* WrP = g_WBr + (size_t)f * NBLK * 128;
    const __half* WiP = g_WBi + (size_t)f * NBLK * 128;

#pragma unroll
    for (int it = 0; it < 8; ++it) {      // A: 2048 x 16B
        int idx = tid + it * 256;
        int r = idx >> 4, ch = idx & 15;
        cp_async16(sb + sw256(r, ch), Xsrc + r * 256 + ch * 16);
    }
#pragma unroll
    for (int it = 0; it < 4; ++it) {      // B: 1024 x 16B each plane
        int idx = tid + it * 256;
        int r = idx >> 4, ch = idx & 15;
        cp_async16(sb + 32768 + sw256(r, ch), WrP + r * 128 + ch * 8);
        cp_async16(sb + 49152 + sw256(r, ch), WiP + r * 128 + ch * 8);
    }
    CP_COMMIT();
    CP_WAIT0();
    __syncthreads();

    const int wm = (wid >> 1) * 32;
    const int wn = (wid & 1) * 32;
    float aR[2][4][4] = {}, aI[2][4][4] = {};

#pragma unroll
    for (int kc = 0; kc < 8; ++kc) {
        uint32_t a[2][4], br[2][4], bi[2][4];
#pragma unroll
        for (int mt = 0; mt < 2; ++mt) {
            int row = wm + mt * 16 + (lane & 15);
            int ch = kc * 2 + (lane >> 4);
            ldsm_x4(a[mt], sb + sw256(row, ch));
        }
#pragma unroll
        for (int bt = 0; bt < 2; ++bt) {
            int row = wn + bt * 16 + (lane >> 4) * 8 + (lane & 7);
            int ch = kc * 2 + ((lane & 15) >> 3);
            ldsm_x4(br[bt], sb + 32768 + sw256(row, ch));
            ldsm_x4(bi[bt], sb + 49152 + sw256(row, ch));
        }
#pragma unroll
        for (int mt = 0; mt < 2; ++mt)
#pragma unroll
            for (int nt = 0; nt < 4; ++nt) {
                mma16816(aR[mt][nt], a[mt], &br[nt >> 1][(nt & 1) * 2]);
                mma16816(aI[mt][nt], a[mt], &bi[nt >> 1][(nt & 1) * 2]);
            }
    }

    uint32_t* Y = reinterpret_cast<uint32_t*>(g_Y2) +
                  (size_t)f * RROWS + (size_t)t0 * 64;
#pragma unroll
    for (int mt = 0; mt < 2; ++mt)
#pragma unroll
        for (int nt = 0; nt < 4; ++nt) {
            int row = wm + mt * 16 + (lane >> 2);
            int col = wn + nt * 8 + (lane & 3) * 2;
            Y[(size_t)row * 64 + col] =
                h2u(__floats2half2_rn(aR[mt][nt][0], aI[mt][nt][0]));
            Y[(size_t)row * 64 + col + 1] =
                h2u(__floats2half2_rn(aR[mt][nt][1], aI[mt][nt][1]));
            Y[(size_t)(row + 8) * 64 + col] =
                h2u(__floats2half2_rn(aR[mt][nt][2], aI[mt][nt][2]));
            Y[(size_t)(row + 8) * 64 + col + 1] =
                h2u(__floats2half2_rn(aR[mt][nt][3], aI[mt][nt][3]));
        }
}

// ----------------------------------------------------------------------------
// K3: inverse DFT GEMM.  M=262144 (r=t*64+o), N=64, K=66->80.
// 256 threads, 256 rows/CTA.  A 256x176B @0 (45056B); B image @45056 (11264B).
// A row k bytes: f*4 -> (Yr_f, Yi_f) pair; cols 66..79 zero.
// ----------------------------------------------------------------------------
__global__ void __launch_bounds__(256, 2) k3_idft(float* __restrict__ out) {
    extern __shared__ __align__(128) char dsm[];
    const uint32_t sb = smem_u32(dsm);
    const uint32_t sbB = sb + 45056;
    const int tid = threadIdx.x;
    const int wid = tid >> 5, lane = tid & 31;
    const int r0 = (int)blockIdx.x * 256;

    // B image: 704 x 16B
#pragma unroll
    for (int it = 0; it < 3; ++it) {
        int idx = tid + it * 256;
        if (idx < 704) cp_async16(sbB + idx * 16, g_Bi_img + idx * 8);
    }
    // A: one row per thread; zero pad then 33 x 4B cp.async
    {
        const uint32_t arow = sb + tid * 176;
#pragma unroll
        for (int j = 0; j < 7; ++j)
            *reinterpret_cast<uint32_t*>(dsm + tid * 176 + 132 + j * 4) = 0u;
        const char* ysrc = reinterpret_cast<const char*>(g_Y2) +
                           ((size_t)r0 + tid) * 4;
#pragma unroll
        for (int f = 0; f < NFREQ; ++f)
            cp_async4(arow + f * 4, ysrc + (size_t)f * RROWS * 4);
    }
    CP_COMMIT();
    CP_WAIT0();
    __syncthreads();

    const int wm = wid * 32;
    float acc[2][8][4] = {};
#pragma unroll
    for (int kc = 0; kc < 5; ++kc) {
        uint32_t a[2][4], b[4][4];
#pragma unroll
        for (int mt = 0; mt < 2; ++mt) {
            int row = wm + mt * 16 + (lane & 15);
            int ch = kc * 2 + (lane >> 4);
            ldsm_x4(a[mt], sb + row * 176 + ch * 16);
        }
#pragma unroll
        for (int bt = 0; bt < 4; ++bt) {
            int row = bt * 16 + (lane >> 4) * 8 + (lane & 7);
            int ch = kc * 2 + ((lane & 15) >> 3);
            ldsm_x4(b[bt], sbB + row * 176 + ch * 16);
        }
#pragma unroll
        for (int mt = 0; mt < 2; ++mt)
#pragma unroll
            for (int nt = 0; nt < 8; ++nt)
                mma16816(acc[mt][nt], a[mt], &b[nt >> 1][(nt & 1) * 2]);
    }

#pragma unroll
    for (int mt = 0; mt < 2; ++mt)
#pragma unroll
        for (int nt = 0; nt < 8; ++nt) {
            int row = r0 + wm + mt * 16 + (lane >> 2);
            int col = nt * 8 + (lane & 3) * 2;
            *reinterpret_cast<float2*>(out + (size_t)row * 64 + col) =
                make_float2(acc[mt][nt][0], acc[mt][nt][1]);
            *reinterpret_cast<float2*>(out + (size_t)(row + 8) * 64 + col) =
                make_float2(acc[mt][nt][2], acc[mt][nt][3]);
        }
}

// ----------------------------------------------------------------------------
// Host entry
// ----------------------------------------------------------------------------
extern "C" void kernel_launch(void* const* d_in, const int* in_sizes, int n_in,
                              void* d_out, int out_size) {
    const float* x       = (const float*)d_in[0];
    const float* params  = (const float*)d_in[1];
    const float* weights = (const float*)d_in[2];
    float* out = (float*)d_out;

    k_tables<<<1, 128>>>();
    kw_fft<<<NBLK * NBLK, 64>>>(params, weights);
    k1_dft<<<RROWS / 128, 128>>>(x);

    cudaFuncSetAttribute(k2_cgemm, cudaFuncAttributeMaxDynamicSharedMemorySize,
                         65536);
    k2_cgemm<<<NFREQ * 32, 256, 65536>>>();

    cudaFuncSetAttribute(k3_idft, cudaFuncAttributeMaxDynamicSharedMemorySize,
                         56320);
    k3_idft<<<RROWS / 256, 256, 56320>>>(out);
}